// round 14
// baseline (speedup 1.0000x reference)
#include <cuda_runtime.h>
#include <cuda_fp16.h>
#include <math.h>
#include <stdint.h>

#define T_TOK 4096
#define DDIM  1024
#define HDIM  4096
#define NEXP  8

#define BM 128
#define BN 128
#define BK 64
#define ASTRIDE 72   // halves per SMEM row (64 + 8 pad => 144B; ldmatrix conflict-free)
#define STAGES 3

// ---------------- device scratch ----------------
__device__ int   g_offsets[NEXP + 1];
__device__ int   g_topi[T_TOK * 2];
__device__ float g_topw[T_TOK * 2];
__device__ int   g_token[T_TOK * 2];
__device__ float g_weight[T_TOK * 2];
__device__ __half g_h[(size_t)T_TOK * 2 * HDIM];      // 67 MB gelu(h) fp16
__device__ __half g_xh[(size_t)T_TOK * DDIM];         // 8 MB  x fp16
__device__ __half g_w1h[(size_t)NEXP * HDIM * DDIM];  // 67 MB w1 fp16
__device__ __half g_w2h[(size_t)NEXP * DDIM * HDIM];  // 67 MB w2 fp16

// ---------------- helpers ----------------
__device__ __forceinline__ uint32_t smem_u32(const void* p) {
    uint32_t a;
    asm("{ .reg .u64 t; cvta.to.shared.u64 t, %1; cvt.u32.u64 %0, t; }" : "=r"(a) : "l"(p));
    return a;
}
__device__ __forceinline__ void cp16(uint32_t dst, const void* src, int sz) {
    asm volatile("cp.async.cg.shared.global [%0], [%1], 16, %2;"
                 :: "r"(dst), "l"(src), "r"(sz) : "memory");
}
#define CP_COMMIT() asm volatile("cp.async.commit_group;" ::: "memory")
#define CP_WAIT(N)  asm volatile("cp.async.wait_group %0;" :: "n"(N) : "memory")

__device__ __forceinline__ void ldmx4(uint32_t* r, uint32_t addr) {
    asm volatile("ldmatrix.sync.aligned.m8n8.x4.shared.b16 {%0,%1,%2,%3}, [%4];"
                 : "=r"(r[0]), "=r"(r[1]), "=r"(r[2]), "=r"(r[3]) : "r"(addr));
}
__device__ __forceinline__ void mma16(float* d, const uint32_t* a, uint32_t b0, uint32_t b1) {
    asm volatile(
        "mma.sync.aligned.m16n8k16.row.col.f32.f16.f16.f32 "
        "{%0,%1,%2,%3}, {%4,%5,%6,%7}, {%8,%9}, {%0,%1,%2,%3};"
        : "+f"(d[0]), "+f"(d[1]), "+f"(d[2]), "+f"(d[3])
        : "r"(a[0]), "r"(a[1]), "r"(a[2]), "r"(a[3]), "r"(b0), "r"(b1));
}

// ---------------- router ----------------
__global__ void k_router(const float* __restrict__ x, const float* __restrict__ rw) {
    __shared__ float srw[NEXP * DDIM];
    for (int i = threadIdx.x; i < NEXP * DDIM; i += blockDim.x) srw[i] = rw[i];
    __syncthreads();

    int warp = threadIdx.x >> 5, lane = threadIdx.x & 31;
    int t = blockIdx.x * 8 + warp;
    if (t >= T_TOK) return;
    const float* xr = x + (size_t)t * DDIM;

    float acc[NEXP];
#pragma unroll
    for (int e = 0; e < NEXP; e++) acc[e] = 0.0f;
    for (int d = lane; d < DDIM; d += 32) {
        float xv = xr[d];
#pragma unroll
        for (int e = 0; e < NEXP; e++) acc[e] += xv * srw[e * DDIM + d];
    }
#pragma unroll
    for (int off = 16; off > 0; off >>= 1)
#pragma unroll
        for (int e = 0; e < NEXP; e++) acc[e] += __shfl_down_sync(0xffffffffu, acc[e], off);

    if (lane == 0) {
        float mx = acc[0];
#pragma unroll
        for (int e = 1; e < NEXP; e++) mx = fmaxf(mx, acc[e]);
        float p[NEXP];
#pragma unroll
        for (int e = 0; e < NEXP; e++) p[e] = expf(acc[e] - mx);
        int i0 = 0;
#pragma unroll
        for (int e = 1; e < NEXP; e++) if (p[e] > p[i0]) i0 = e;
        int i1 = (i0 == 0) ? 1 : 0;
#pragma unroll
        for (int e = 0; e < NEXP; e++) if (e != i0 && p[e] > p[i1]) i1 = e;
        float w0 = p[i0], w1 = p[i1];
        float s = w0 + w1;
        w0 /= s; w1 /= s;
        g_topi[2 * t] = i0;     g_topw[2 * t] = w0;
        g_topi[2 * t + 1] = i1; g_topw[2 * t + 1] = w1;
    }
}

// ---------------- fused histogram + offsets + scatter (single block) --------
__global__ void k_scatter_fused() {
    __shared__ int hist[NEXP];
    __shared__ int off[NEXP];
    __shared__ int fill[NEXP];
    int tid = threadIdx.x;
    if (tid < NEXP) hist[tid] = 0;
    __syncthreads();
    for (int i = tid; i < 2 * T_TOK; i += blockDim.x)
        atomicAdd(&hist[g_topi[i]], 1);
    __syncthreads();
    if (tid == 0) {
        int s = 0;
        for (int e = 0; e < NEXP; e++) {
            g_offsets[e] = s; off[e] = s; fill[e] = 0; s += hist[e];
        }
        g_offsets[NEXP] = s;
    }
    __syncthreads();
    for (int i = tid; i < 2 * T_TOK; i += blockDim.x) {
        int e = g_topi[i];
        int pos = off[e] + atomicAdd(&fill[e], 1);
        g_token[pos] = i >> 1;
        g_weight[pos] = g_topw[i];
    }
}

// ---------------- convert x + w1 (main stream) ----------------
__global__ void k_cvt_xw1(const float4* __restrict__ x,
                          const float4* __restrict__ w1,
                          __half2* __restrict__ ox,
                          __half2* __restrict__ ow1) {
    const int N_X = T_TOK * DDIM / 4;
    const int N_W = NEXP * HDIM * DDIM / 4;
    int i = blockIdx.x * blockDim.x + threadIdx.x;
    const float4* src;
    __half2* dst;
    int j;
    if (i < N_X)            { src = x;  dst = ox;  j = i; }
    else if (i < N_X + N_W) { src = w1; dst = ow1; j = i - N_X; }
    else return;
    float4 v = src[j];
    dst[2 * j]     = __floats2half2_rn(v.x, v.y);
    dst[2 * j + 1] = __floats2half2_rn(v.z, v.w);
}

// ---------------- convert w2 + zero out (side stream; overlaps GEMM1) -------
__global__ void k_cvt_w2z(const float4* __restrict__ w2,
                          __half2* __restrict__ ow2,
                          float4* __restrict__ outz) {
    const int N_O = T_TOK * DDIM / 4;
    const int N_W = NEXP * DDIM * HDIM / 4;
    int i = blockIdx.x * blockDim.x + threadIdx.x;
    if (i < N_O) { outz[i] = make_float4(0.f, 0.f, 0.f, 0.f); return; }
    i -= N_O;
    if (i >= N_W) return;
    float4 v = w2[i];
    ow2[2 * i]     = __floats2half2_rn(v.x, v.y);
    ow2[2 * i + 1] = __floats2half2_rn(v.z, v.w);
}

// ---------------- fp16 mma.sync grouped GEMM ----------------
// 3-stage cp.async ring, 1 barrier/chunk, fragment double-buffering,
// modulo-free unroll-by-3 stage rotation.  Split-K capable.
// 8 warps as 2(M) x 4(N): warp tile 64 x 32.
template <int KDIM, int NTOT, bool IS_G1, int KSL>
__global__ __launch_bounds__(256, 2) void k_gemm_mma(
    const __half* __restrict__ A, const __half* __restrict__ W,
    const float* __restrict__ bias, void* __restrict__ outp)
{
    constexpr int A_ST = BM * ASTRIDE;
    constexpr int B_ST = BN * ASTRIDE;
    constexpr int C = KDIM / KSL / BK;

    int zi = blockIdx.z;
    int e = zi / KSL;
    int ksl = zi % KSL;
    int koff = ksl * (KDIM / KSL);

    int base = g_offsets[e];
    int cnt = g_offsets[e + 1] - base;
    int m0 = blockIdx.y * BM;
    if (m0 >= cnt) return;
    int n0 = blockIdx.x * BN;

    extern __shared__ __half smem[];
    uint32_t As_u32 = smem_u32(smem);                 // STAGES x A_ST
    uint32_t Bs_u32 = As_u32 + STAGES * A_ST * 2;     // STAGES x B_ST

    __shared__ int   stok[BM];
    __shared__ float swt[BM];

    int tid = threadIdx.x;
    int wid = tid >> 5, lane = tid & 31;
    int wm = wid & 1, wn = wid >> 1;

    if (tid < BM) {
        bool v = (m0 + tid < cnt);
        stok[tid] = v ? g_token[base + m0 + tid] : -1;
        swt[tid]  = v ? g_weight[base + m0 + tid] : 0.0f;
    }
    __syncthreads();

    const __half* Wbase = W + (size_t)e * NTOT * KDIM + (size_t)n0 * KDIM + koff;

    auto load_chunk = [&](int c, int buf) {
        int k0 = c * BK;
        uint32_t Ab = As_u32 + buf * A_ST * 2;
        uint32_t Bb = Bs_u32 + buf * B_ST * 2;
#pragma unroll
        for (int i = 0; i < 4; i++) {
            int idx = tid + i * 256;
            int row = idx >> 3, q = idx & 7;
            uint32_t dst = Ab + (row * ASTRIDE + q * 8) * 2;
            if (IS_G1) {
                int tok = stok[row];
                const __half* src = (tok >= 0) ? (A + (size_t)tok * KDIM + koff + k0 + q * 8) : A;
                cp16(dst, src, (tok >= 0) ? 16 : 0);
            } else {
                bool v = (m0 + row < cnt);
                const __half* src = v ? (A + (size_t)(base + m0 + row) * KDIM + koff + k0 + q * 8) : A;
                cp16(dst, src, v ? 16 : 0);
            }
        }
#pragma unroll
        for (int i = 0; i < 4; i++) {
            int idx = tid + i * 256;
            int row = idx >> 3, q = idx & 7;
            uint32_t dst = Bb + (row * ASTRIDE + q * 8) * 2;
            cp16(dst, Wbase + (size_t)row * KDIM + k0 + q * 8, 16);
        }
        CP_COMMIT();
    };

    float acc[4][4][4];
#pragma unroll
    for (int mt = 0; mt < 4; mt++)
#pragma unroll
        for (int nt = 0; nt < 4; nt++)
#pragma unroll
            for (int r = 0; r < 4; r++) acc[mt][nt][r] = 0.0f;

    load_chunk(0, 0);
    load_chunk(1, 1);

    // one pipeline step: consume stage `buf` for chunk `c`, prefetch c+2
    auto step = [&](int c, int buf) {
        if (c < C - 1) { CP_WAIT(1); } else { CP_WAIT(0); }
        __syncthreads();
        if (c + 2 < C) load_chunk(c + 2, (buf + 2) % STAGES);  // folds when buf literal

        uint32_t Ab = As_u32 + buf * A_ST * 2;
        uint32_t Bb = Bs_u32 + buf * B_ST * 2;

        // fragment double-buffering across the 4 k-steps
        uint32_t a[2][4][4], b[2][2][4];
        auto ldf = [&](int ks, uint32_t (&af)[4][4], uint32_t (&bf)[2][4]) {
            int kh = ks * 16 + ((lane >> 4) << 3);
#pragma unroll
            for (int mt = 0; mt < 4; mt++) {
                int r = wm * 64 + mt * 16 + (lane & 15);
                ldmx4(af[mt], Ab + (r * ASTRIDE + kh) * 2);
            }
#pragma unroll
            for (int np = 0; np < 2; np++) {
                int r = wn * 32 + np * 16 + (lane & 15);
                ldmx4(bf[np], Bb + (r * ASTRIDE + kh) * 2);
            }
        };
        ldf(0, a[0], b[0]);
#pragma unroll
        for (int ks = 0; ks < BK / 16; ks++) {
            int cur = ks & 1;
            if (ks < BK / 16 - 1) ldf(ks + 1, a[cur ^ 1], b[cur ^ 1]);
#pragma unroll
            for (int mt = 0; mt < 4; mt++)
#pragma unroll
                for (int np = 0; np < 2; np++) {
                    mma16(acc[mt][2 * np + 0], a[cur][mt], b[cur][np][0], b[cur][np][2]);
                    mma16(acc[mt][2 * np + 1], a[cur][mt], b[cur][np][1], b[cur][np][3]);
                }
        }
    };

    // modulo-free steady state: 3 steps per iteration with literal stage ids
    int c = 0;
#pragma unroll 1
    for (; c + 3 <= C; c += 3) {
        step(c,     0);
        step(c + 1, 1);
        step(c + 2, 2);
    }
    if (c < C) { step(c, 0); c++; }
    if (c < C) { step(c, 1); }

    // epilogue
    bool add_bias = (ksl == 0);
#pragma unroll
    for (int mt = 0; mt < 4; mt++) {
#pragma unroll
        for (int nt = 0; nt < 4; nt++) {
#pragma unroll
            for (int half = 0; half < 2; half++) {
                int m = wm * 64 + mt * 16 + (lane >> 2) + half * 8;
                if (m0 + m >= cnt) continue;
                int ncol = n0 + wn * 32 + nt * 8 + (lane & 3) * 2;
                float b0 = add_bias ? bias[e * NTOT + ncol]     : 0.0f;
                float b1 = add_bias ? bias[e * NTOT + ncol + 1] : 0.0f;
                float v0 = acc[mt][nt][half * 2 + 0] + b0;
                float v1 = acc[mt][nt][half * 2 + 1] + b1;
                if (IS_G1) {
                    float g0 = 0.5f * v0 * (1.0f + erff(v0 * 0.70710678118654752f));
                    float g1 = 0.5f * v1 * (1.0f + erff(v1 * 0.70710678118654752f));
                    __half2* dst = (__half2*)((__half*)outp +
                                   (size_t)(base + m0 + m) * NTOT + ncol);
                    *dst = __floats2half2_rn(g0, g1);
                } else {
                    int tok = stok[m];
                    float w = swt[m];
                    float* o = (float*)outp + (size_t)tok * NTOT + ncol;
                    atomicAdd(o,     w * v0);
                    atomicAdd(o + 1, w * v1);
                }
            }
        }
    }
}

// ---------------- launch (R10 topology) ----------------
extern "C" void kernel_launch(void* const* d_in, const int* in_sizes, int n_in,
                              void* d_out, int out_size) {
    const float* x   = (const float*)d_in[0];
    const float* rw  = (const float*)d_in[1];
    const float* w1  = (const float*)d_in[2];
    const float* b1  = (const float*)d_in[3];
    const float* w2  = (const float*)d_in[4];
    const float* b2  = (const float*)d_in[5];
    float* out = (float*)d_out;

    const int SMEM_BYTES = STAGES * (BM + BN) * ASTRIDE * 2;   // 110592

    static cudaStream_t s_side = 0;
    static cudaEvent_t ev_fork = 0, ev_scat = 0, ev_cvt1 = 0, ev_w2 = 0;
    static int init_done = 0;
    if (!init_done) {
        cudaFuncSetAttribute(k_gemm_mma<DDIM, HDIM, true, 1>,
                             cudaFuncAttributeMaxDynamicSharedMemorySize, SMEM_BYTES);
        cudaFuncSetAttribute(k_gemm_mma<HDIM, DDIM, false, 2>,
                             cudaFuncAttributeMaxDynamicSharedMemorySize, SMEM_BYTES);
        cudaStreamCreateWithFlags(&s_side, cudaStreamNonBlocking);
        cudaEventCreateWithFlags(&ev_fork, cudaEventDisableTiming);
        cudaEventCreateWithFlags(&ev_scat, cudaEventDisableTiming);
        cudaEventCreateWithFlags(&ev_cvt1, cudaEventDisableTiming);
        cudaEventCreateWithFlags(&ev_w2,   cudaEventDisableTiming);
        init_done = 1;
    }

    __half *gh, *gxh, *gw1h, *gw2h;
    cudaGetSymbolAddress((void**)&gh,   g_h);
    cudaGetSymbolAddress((void**)&gxh,  g_xh);
    cudaGetSymbolAddress((void**)&gw1h, g_w1h);
    cudaGetSymbolAddress((void**)&gw2h, g_w2h);

    const int N_O = T_TOK * DDIM / 4;
    const int N_X = T_TOK * DDIM / 4;
    const int N_W = NEXP * HDIM * DDIM / 4;

    // fork side stream
    cudaEventRecord(ev_fork, 0);
    cudaStreamWaitEvent(s_side, ev_fork, 0);

    // main: convert x + w1
    k_cvt_xw1<<<(N_X + N_W + 255) / 256, 256>>>(
        (const float4*)x, (const float4*)w1, (__half2*)gxh, (__half2*)gw1h);
    cudaEventRecord(ev_cvt1, 0);

    // side: router + scatter, concurrent with cvt_xw1
    k_router<<<T_TOK / 8, 256, 0, s_side>>>(x, rw);
    k_scatter_fused<<<1, 1024, 0, s_side>>>();
    cudaEventRecord(ev_scat, s_side);

    // side: w2 convert + out zero AFTER cvt_xw1 completes -> overlaps GEMM1
    cudaStreamWaitEvent(s_side, ev_cvt1, 0);
    k_cvt_w2z<<<(N_O + N_W + 255) / 256, 256, 0, s_side>>>(
        (const float4*)w2, (__half2*)gw2h, (float4*)out);
    cudaEventRecord(ev_w2, s_side);

    // main: GEMM1 after scatter
    cudaStreamWaitEvent(0, ev_scat, 0);
    k_gemm_mma<DDIM, HDIM, true, 1>
        <<<dim3(HDIM / BN, T_TOK / BM, NEXP), 256, SMEM_BYTES>>>(gxh, gw1h, b1, gh);

    // main: GEMM2 after w2 convert (split-K = 2)
    cudaStreamWaitEvent(0, ev_w2, 0);
    k_gemm_mma<HDIM, DDIM, false, 2>
        <<<dim3(DDIM / BN, T_TOK / BM, NEXP * 2), 256, SMEM_BYTES>>>(gh, gw2h, b2, out);
}

// round 15
// speedup vs baseline: 1.0218x; 1.0218x over previous
#include <cuda_runtime.h>
#include <cuda_fp16.h>
#include <math.h>
#include <stdint.h>

#define T_TOK 4096
#define DDIM  1024
#define HDIM  4096
#define NEXP  8

#define BM 128
#define BN 128
#define BK 64
#define ASTRIDE 72   // halves per SMEM row (64 + 8 pad => 144B; ldmatrix conflict-free)
#define STAGES 3
#define MAXTILES 71  // sum ceil(cnt_e/128) <= 8192/128 + (NEXP-1) = 71

// ---------------- device scratch ----------------
__device__ int   g_offsets[NEXP + 1];
__device__ int   g_topi[T_TOK * 2];
__device__ float g_topw[T_TOK * 2];
__device__ int   g_token[T_TOK * 2];
__device__ float g_weight[T_TOK * 2];
__device__ int   g_tiles[MAXTILES];   // (e << 20) | m0
__device__ int   g_ntiles;
__device__ __half g_h[(size_t)T_TOK * 2 * HDIM];      // 67 MB gelu(h) fp16
__device__ __half g_xh[(size_t)T_TOK * DDIM];         // 8 MB  x fp16
__device__ __half g_w1h[(size_t)NEXP * HDIM * DDIM];  // 67 MB w1 fp16
__device__ __half g_w2h[(size_t)NEXP * DDIM * HDIM];  // 67 MB w2 fp16

// ---------------- helpers ----------------
__device__ __forceinline__ uint32_t smem_u32(const void* p) {
    uint32_t a;
    asm("{ .reg .u64 t; cvta.to.shared.u64 t, %1; cvt.u32.u64 %0, t; }" : "=r"(a) : "l"(p));
    return a;
}
__device__ __forceinline__ void cp16(uint32_t dst, const void* src, int sz) {
    asm volatile("cp.async.cg.shared.global [%0], [%1], 16, %2;"
                 :: "r"(dst), "l"(src), "r"(sz) : "memory");
}
#define CP_COMMIT() asm volatile("cp.async.commit_group;" ::: "memory")
#define CP_WAIT(N)  asm volatile("cp.async.wait_group %0;" :: "n"(N) : "memory")

__device__ __forceinline__ void ldmx4(uint32_t* r, uint32_t addr) {
    asm volatile("ldmatrix.sync.aligned.m8n8.x4.shared.b16 {%0,%1,%2,%3}, [%4];"
                 : "=r"(r[0]), "=r"(r[1]), "=r"(r[2]), "=r"(r[3]) : "r"(addr));
}
__device__ __forceinline__ void mma16(float* d, const uint32_t* a, uint32_t b0, uint32_t b1) {
    asm volatile(
        "mma.sync.aligned.m16n8k16.row.col.f32.f16.f16.f32 "
        "{%0,%1,%2,%3}, {%4,%5,%6,%7}, {%8,%9}, {%0,%1,%2,%3};"
        : "+f"(d[0]), "+f"(d[1]), "+f"(d[2]), "+f"(d[3])
        : "r"(a[0]), "r"(a[1]), "r"(a[2]), "r"(a[3]), "r"(b0), "r"(b1));
}

// ---------------- router ----------------
__global__ void k_router(const float* __restrict__ x, const float* __restrict__ rw) {
    __shared__ float srw[NEXP * DDIM];
    for (int i = threadIdx.x; i < NEXP * DDIM; i += blockDim.x) srw[i] = rw[i];
    __syncthreads();

    int warp = threadIdx.x >> 5, lane = threadIdx.x & 31;
    int t = blockIdx.x * 8 + warp;
    if (t >= T_TOK) return;
    const float* xr = x + (size_t)t * DDIM;

    float acc[NEXP];
#pragma unroll
    for (int e = 0; e < NEXP; e++) acc[e] = 0.0f;
    for (int d = lane; d < DDIM; d += 32) {
        float xv = xr[d];
#pragma unroll
        for (int e = 0; e < NEXP; e++) acc[e] += xv * srw[e * DDIM + d];
    }
#pragma unroll
    for (int off = 16; off > 0; off >>= 1)
#pragma unroll
        for (int e = 0; e < NEXP; e++) acc[e] += __shfl_down_sync(0xffffffffu, acc[e], off);

    if (lane == 0) {
        float mx = acc[0];
#pragma unroll
        for (int e = 1; e < NEXP; e++) mx = fmaxf(mx, acc[e]);
        float p[NEXP];
#pragma unroll
        for (int e = 0; e < NEXP; e++) p[e] = expf(acc[e] - mx);
        int i0 = 0;
#pragma unroll
        for (int e = 1; e < NEXP; e++) if (p[e] > p[i0]) i0 = e;
        int i1 = (i0 == 0) ? 1 : 0;
#pragma unroll
        for (int e = 0; e < NEXP; e++) if (e != i0 && p[e] > p[i1]) i1 = e;
        float w0 = p[i0], w1 = p[i1];
        float s = w0 + w1;
        w0 /= s; w1 /= s;
        g_topi[2 * t] = i0;     g_topw[2 * t] = w0;
        g_topi[2 * t + 1] = i1; g_topw[2 * t + 1] = w1;
    }
}

// ------- fused histogram + offsets + scatter + tile list (single block) -----
__global__ void k_scatter_fused() {
    __shared__ int hist[NEXP];
    __shared__ int off[NEXP];
    __shared__ int fill[NEXP];
    int tid = threadIdx.x;
    if (tid < NEXP) hist[tid] = 0;
    __syncthreads();
    for (int i = tid; i < 2 * T_TOK; i += blockDim.x)
        atomicAdd(&hist[g_topi[i]], 1);
    __syncthreads();
    if (tid == 0) {
        int s = 0;
        for (int e = 0; e < NEXP; e++) {
            g_offsets[e] = s; off[e] = s; fill[e] = 0; s += hist[e];
        }
        g_offsets[NEXP] = s;
        // dense m-tile work list
        int t = 0;
        for (int e = 0; e < NEXP; e++)
            for (int m0 = 0; m0 < hist[e]; m0 += BM)
                g_tiles[t++] = (e << 20) | m0;
        g_ntiles = t;
    }
    __syncthreads();
    for (int i = tid; i < 2 * T_TOK; i += blockDim.x) {
        int e = g_topi[i];
        int pos = off[e] + atomicAdd(&fill[e], 1);
        g_token[pos] = i >> 1;
        g_weight[pos] = g_topw[i];
    }
}

// ---------------- convert x + w1 (main stream) ----------------
__global__ void k_cvt_xw1(const float4* __restrict__ x,
                          const float4* __restrict__ w1,
                          __half2* __restrict__ ox,
                          __half2* __restrict__ ow1) {
    const int N_X = T_TOK * DDIM / 4;
    const int N_W = NEXP * HDIM * DDIM / 4;
    int i = blockIdx.x * blockDim.x + threadIdx.x;
    const float4* src;
    __half2* dst;
    int j;
    if (i < N_X)            { src = x;  dst = ox;  j = i; }
    else if (i < N_X + N_W) { src = w1; dst = ow1; j = i - N_X; }
    else return;
    float4 v = src[j];
    dst[2 * j]     = __floats2half2_rn(v.x, v.y);
    dst[2 * j + 1] = __floats2half2_rn(v.z, v.w);
}

// ---------------- convert w2 + zero out (side stream; overlaps GEMM1) -------
__global__ void k_cvt_w2z(const float4* __restrict__ w2,
                          __half2* __restrict__ ow2,
                          float4* __restrict__ outz) {
    const int N_O = T_TOK * DDIM / 4;
    const int N_W = NEXP * DDIM * HDIM / 4;
    int i = blockIdx.x * blockDim.x + threadIdx.x;
    if (i < N_O) { outz[i] = make_float4(0.f, 0.f, 0.f, 0.f); return; }
    i -= N_O;
    if (i >= N_W) return;
    float4 v = w2[i];
    ow2[2 * i]     = __floats2half2_rn(v.x, v.y);
    ow2[2 * i + 1] = __floats2half2_rn(v.z, v.w);
}

// ---------------- fp16 mma.sync grouped GEMM ----------------
// 3-stage cp.async ring, 1 barrier/chunk, fragment double-buffering,
// modulo-free unroll-by-3, compacted tile list.  Split-K capable.
// 8 warps as 2(M) x 4(N): warp tile 64 x 32.
template <int KDIM, int NTOT, bool IS_G1, int KSL>
__global__ __launch_bounds__(256, 2) void k_gemm_mma(
    const __half* __restrict__ A, const __half* __restrict__ W,
    const float* __restrict__ bias, void* __restrict__ outp)
{
    constexpr int A_ST = BM * ASTRIDE;
    constexpr int B_ST = BN * ASTRIDE;
    constexpr int C = KDIM / KSL / BK;

    if (blockIdx.y >= (unsigned)g_ntiles) return;
    int tile = g_tiles[blockIdx.y];
    int e = tile >> 20;
    int m0 = tile & 0xFFFFF;
    int ksl = blockIdx.z;
    int koff = ksl * (KDIM / KSL);

    int base = g_offsets[e];
    int cnt = g_offsets[e + 1] - base;
    int n0 = blockIdx.x * BN;

    extern __shared__ __half smem[];
    uint32_t As_u32 = smem_u32(smem);                 // STAGES x A_ST
    uint32_t Bs_u32 = As_u32 + STAGES * A_ST * 2;     // STAGES x B_ST

    __shared__ int   stok[BM];
    __shared__ float swt[BM];

    int tid = threadIdx.x;
    int wid = tid >> 5, lane = tid & 31;
    int wm = wid & 1, wn = wid >> 1;

    if (tid < BM) {
        bool v = (m0 + tid < cnt);
        stok[tid] = v ? g_token[base + m0 + tid] : -1;
        swt[tid]  = v ? g_weight[base + m0 + tid] : 0.0f;
    }
    __syncthreads();

    const __half* Wbase = W + (size_t)e * NTOT * KDIM + (size_t)n0 * KDIM + koff;

    auto load_chunk = [&](int c, int buf) {
        int k0 = c * BK;
        uint32_t Ab = As_u32 + buf * A_ST * 2;
        uint32_t Bb = Bs_u32 + buf * B_ST * 2;
#pragma unroll
        for (int i = 0; i < 4; i++) {
            int idx = tid + i * 256;
            int row = idx >> 3, q = idx & 7;
            uint32_t dst = Ab + (row * ASTRIDE + q * 8) * 2;
            if (IS_G1) {
                int tok = stok[row];
                const __half* src = (tok >= 0) ? (A + (size_t)tok * KDIM + koff + k0 + q * 8) : A;
                cp16(dst, src, (tok >= 0) ? 16 : 0);
            } else {
                bool v = (m0 + row < cnt);
                const __half* src = v ? (A + (size_t)(base + m0 + row) * KDIM + koff + k0 + q * 8) : A;
                cp16(dst, src, v ? 16 : 0);
            }
        }
#pragma unroll
        for (int i = 0; i < 4; i++) {
            int idx = tid + i * 256;
            int row = idx >> 3, q = idx & 7;
            uint32_t dst = Bb + (row * ASTRIDE + q * 8) * 2;
            cp16(dst, Wbase + (size_t)row * KDIM + k0 + q * 8, 16);
        }
        CP_COMMIT();
    };

    float acc[4][4][4];
#pragma unroll
    for (int mt = 0; mt < 4; mt++)
#pragma unroll
        for (int nt = 0; nt < 4; nt++)
#pragma unroll
            for (int r = 0; r < 4; r++) acc[mt][nt][r] = 0.0f;

    load_chunk(0, 0);
    load_chunk(1, 1);

    // one pipeline step: consume stage `buf` for chunk `c`, prefetch c+2
    auto step = [&](int c, int buf) {
        if (c < C - 1) { CP_WAIT(1); } else { CP_WAIT(0); }
        __syncthreads();
        if (c + 2 < C) load_chunk(c + 2, (buf + 2) % STAGES);  // folds when buf literal

        uint32_t Ab = As_u32 + buf * A_ST * 2;
        uint32_t Bb = Bs_u32 + buf * B_ST * 2;

        // fragment double-buffering across the 4 k-steps
        uint32_t a[2][4][4], b[2][2][4];
        auto ldf = [&](int ks, uint32_t (&af)[4][4], uint32_t (&bf)[2][4]) {
            int kh = ks * 16 + ((lane >> 4) << 3);
#pragma unroll
            for (int mt = 0; mt < 4; mt++) {
                int r = wm * 64 + mt * 16 + (lane & 15);
                ldmx4(af[mt], Ab + (r * ASTRIDE + kh) * 2);
            }
#pragma unroll
            for (int np = 0; np < 2; np++) {
                int r = wn * 32 + np * 16 + (lane & 15);
                ldmx4(bf[np], Bb + (r * ASTRIDE + kh) * 2);
            }
        };
        ldf(0, a[0], b[0]);
#pragma unroll
        for (int ks = 0; ks < BK / 16; ks++) {
            int cur = ks & 1;
            if (ks < BK / 16 - 1) ldf(ks + 1, a[cur ^ 1], b[cur ^ 1]);
#pragma unroll
            for (int mt = 0; mt < 4; mt++)
#pragma unroll
                for (int np = 0; np < 2; np++) {
                    mma16(acc[mt][2 * np + 0], a[cur][mt], b[cur][np][0], b[cur][np][2]);
                    mma16(acc[mt][2 * np + 1], a[cur][mt], b[cur][np][1], b[cur][np][3]);
                }
        }
    };

    // modulo-free steady state: 3 steps per iteration with literal stage ids
    int c = 0;
#pragma unroll 1
    for (; c + 3 <= C; c += 3) {
        step(c,     0);
        step(c + 1, 1);
        step(c + 2, 2);
    }
    if (c < C) { step(c, 0); c++; }
    if (c < C) { step(c, 1); }

    // epilogue
    bool add_bias = (ksl == 0);
#pragma unroll
    for (int mt = 0; mt < 4; mt++) {
#pragma unroll
        for (int nt = 0; nt < 4; nt++) {
#pragma unroll
            for (int half = 0; half < 2; half++) {
                int m = wm * 64 + mt * 16 + (lane >> 2) + half * 8;
                if (m0 + m >= cnt) continue;
                int ncol = n0 + wn * 32 + nt * 8 + (lane & 3) * 2;
                float b0 = add_bias ? bias[e * NTOT + ncol]     : 0.0f;
                float b1 = add_bias ? bias[e * NTOT + ncol + 1] : 0.0f;
                float v0 = acc[mt][nt][half * 2 + 0] + b0;
                float v1 = acc[mt][nt][half * 2 + 1] + b1;
                if (IS_G1) {
                    float g0 = 0.5f * v0 * (1.0f + erff(v0 * 0.70710678118654752f));
                    float g1 = 0.5f * v1 * (1.0f + erff(v1 * 0.70710678118654752f));
                    __half2* dst = (__half2*)((__half*)outp +
                                   (size_t)(base + m0 + m) * NTOT + ncol);
                    *dst = __floats2half2_rn(g0, g1);
                } else {
                    int tok = stok[m];
                    float w = swt[m];
                    float* o = (float*)outp + (size_t)tok * NTOT + ncol;
                    atomicAdd(o,     w * v0);
                    atomicAdd(o + 1, w * v1);
                }
            }
        }
    }
}

// ---------------- launch (R10 topology, compacted grids) ----------------
extern "C" void kernel_launch(void* const* d_in, const int* in_sizes, int n_in,
                              void* d_out, int out_size) {
    const float* x   = (const float*)d_in[0];
    const float* rw  = (const float*)d_in[1];
    const float* w1  = (const float*)d_in[2];
    const float* b1  = (const float*)d_in[3];
    const float* w2  = (const float*)d_in[4];
    const float* b2  = (const float*)d_in[5];
    float* out = (float*)d_out;

    const int SMEM_BYTES = STAGES * (BM + BN) * ASTRIDE * 2;   // 110592

    static cudaStream_t s_side = 0;
    static cudaEvent_t ev_fork = 0, ev_scat = 0, ev_cvt1 = 0, ev_w2 = 0;
    static int init_done = 0;
    if (!init_done) {
        cudaFuncSetAttribute(k_gemm_mma<DDIM, HDIM, true, 1>,
                             cudaFuncAttributeMaxDynamicSharedMemorySize, SMEM_BYTES);
        cudaFuncSetAttribute(k_gemm_mma<HDIM, DDIM, false, 2>,
                             cudaFuncAttributeMaxDynamicSharedMemorySize, SMEM_BYTES);
        cudaStreamCreateWithFlags(&s_side, cudaStreamNonBlocking);
        cudaEventCreateWithFlags(&ev_fork, cudaEventDisableTiming);
        cudaEventCreateWithFlags(&ev_scat, cudaEventDisableTiming);
        cudaEventCreateWithFlags(&ev_cvt1, cudaEventDisableTiming);
        cudaEventCreateWithFlags(&ev_w2,   cudaEventDisableTiming);
        init_done = 1;
    }

    __half *gh, *gxh, *gw1h, *gw2h;
    cudaGetSymbolAddress((void**)&gh,   g_h);
    cudaGetSymbolAddress((void**)&gxh,  g_xh);
    cudaGetSymbolAddress((void**)&gw1h, g_w1h);
    cudaGetSymbolAddress((void**)&gw2h, g_w2h);

    const int N_O = T_TOK * DDIM / 4;
    const int N_X = T_TOK * DDIM / 4;
    const int N_W = NEXP * HDIM * DDIM / 4;

    // fork side stream
    cudaEventRecord(ev_fork, 0);
    cudaStreamWaitEvent(s_side, ev_fork, 0);

    // main: convert x + w1
    k_cvt_xw1<<<(N_X + N_W + 255) / 256, 256>>>(
        (const float4*)x, (const float4*)w1, (__half2*)gxh, (__half2*)gw1h);
    cudaEventRecord(ev_cvt1, 0);

    // side: router + scatter (+ tile list), concurrent with cvt_xw1
    k_router<<<T_TOK / 8, 256, 0, s_side>>>(x, rw);
    k_scatter_fused<<<1, 1024, 0, s_side>>>();
    cudaEventRecord(ev_scat, s_side);

    // side: w2 convert + out zero AFTER cvt_xw1 completes -> overlaps GEMM1
    cudaStreamWaitEvent(s_side, ev_cvt1, 0);
    k_cvt_w2z<<<(N_O + N_W + 255) / 256, 256, 0, s_side>>>(
        (const float4*)w2, (__half2*)gw2h, (float4*)out);
    cudaEventRecord(ev_w2, s_side);

    // main: GEMM1 after scatter (compacted tile list)
    cudaStreamWaitEvent(0, ev_scat, 0);
    k_gemm_mma<DDIM, HDIM, true, 1>
        <<<dim3(HDIM / BN, MAXTILES, 1), 256, SMEM_BYTES>>>(gxh, gw1h, b1, gh);

    // main: GEMM2 after w2 convert (split-K = 2, compacted tile list)
    cudaStreamWaitEvent(0, ev_w2, 0);
    k_gemm_mma<HDIM, DDIM, false, 2>
        <<<dim3(DDIM / BN, MAXTILES, 2), 256, SMEM_BYTES>>>(gh, gw2h, b2, out);
}

// round 16
// speedup vs baseline: 1.0226x; 1.0007x over previous
#include <cuda_runtime.h>
#include <cuda_fp16.h>
#include <math.h>
#include <stdint.h>

#define T_TOK 4096
#define DDIM  1024
#define HDIM  4096
#define NEXP  8

#define BM 128
#define BN 128
#define BK 64
#define ASTRIDE 72   // halves per SMEM row (64 + 8 pad => 144B; ldmatrix conflict-free)
#define STAGES 3
#define MAXTILES 71  // sum ceil(cnt_e/128) <= 8192/128 + (NEXP-1) = 71

// ---------------- device scratch ----------------
__device__ int   g_offsets[NEXP + 1];
__device__ int   g_topi[T_TOK * 2];
__device__ float g_topw[T_TOK * 2];
__device__ int   g_token[T_TOK * 2];
__device__ float g_weight[T_TOK * 2];
__device__ int   g_tiles[MAXTILES];   // (e << 20) | m0
__device__ int   g_ntiles;
__device__ __half g_h[(size_t)T_TOK * 2 * HDIM];      // 67 MB gelu(h) fp16
__device__ __half g_xh[(size_t)T_TOK * DDIM];         // 8 MB  x fp16
__device__ __half g_w1h[(size_t)NEXP * HDIM * DDIM];  // 67 MB w1 fp16
__device__ __half g_w2h[(size_t)NEXP * DDIM * HDIM];  // 67 MB w2 fp16

// ---------------- helpers ----------------
__device__ __forceinline__ uint32_t smem_u32(const void* p) {
    uint32_t a;
    asm("{ .reg .u64 t; cvta.to.shared.u64 t, %1; cvt.u32.u64 %0, t; }" : "=r"(a) : "l"(p));
    return a;
}
__device__ __forceinline__ void cp16(uint32_t dst, const void* src, int sz) {
    asm volatile("cp.async.cg.shared.global [%0], [%1], 16, %2;"
                 :: "r"(dst), "l"(src), "r"(sz) : "memory");
}
#define CP_COMMIT() asm volatile("cp.async.commit_group;" ::: "memory")
#define CP_WAIT(N)  asm volatile("cp.async.wait_group %0;" :: "n"(N) : "memory")

__device__ __forceinline__ void ldmx4(uint32_t* r, uint32_t addr) {
    asm volatile("ldmatrix.sync.aligned.m8n8.x4.shared.b16 {%0,%1,%2,%3}, [%4];"
                 : "=r"(r[0]), "=r"(r[1]), "=r"(r[2]), "=r"(r[3]) : "r"(addr));
}
__device__ __forceinline__ void mma16(float* d, const uint32_t* a, uint32_t b0, uint32_t b1) {
    asm volatile(
        "mma.sync.aligned.m16n8k16.row.col.f32.f16.f16.f32 "
        "{%0,%1,%2,%3}, {%4,%5,%6,%7}, {%8,%9}, {%0,%1,%2,%3};"
        : "+f"(d[0]), "+f"(d[1]), "+f"(d[2]), "+f"(d[3])
        : "r"(a[0]), "r"(a[1]), "r"(a[2]), "r"(a[3]), "r"(b0), "r"(b1));
}

// ---------------- router ----------------
__global__ void k_router(const float* __restrict__ x, const float* __restrict__ rw) {
    __shared__ float srw[NEXP * DDIM];
    for (int i = threadIdx.x; i < NEXP * DDIM; i += blockDim.x) srw[i] = rw[i];
    __syncthreads();

    int warp = threadIdx.x >> 5, lane = threadIdx.x & 31;
    int t = blockIdx.x * 8 + warp;
    if (t >= T_TOK) return;
    const float* xr = x + (size_t)t * DDIM;

    float acc[NEXP];
#pragma unroll
    for (int e = 0; e < NEXP; e++) acc[e] = 0.0f;
    for (int d = lane; d < DDIM; d += 32) {
        float xv = xr[d];
#pragma unroll
        for (int e = 0; e < NEXP; e++) acc[e] += xv * srw[e * DDIM + d];
    }
#pragma unroll
    for (int off = 16; off > 0; off >>= 1)
#pragma unroll
        for (int e = 0; e < NEXP; e++) acc[e] += __shfl_down_sync(0xffffffffu, acc[e], off);

    if (lane == 0) {
        float mx = acc[0];
#pragma unroll
        for (int e = 1; e < NEXP; e++) mx = fmaxf(mx, acc[e]);
        float p[NEXP];
#pragma unroll
        for (int e = 0; e < NEXP; e++) p[e] = expf(acc[e] - mx);
        int i0 = 0;
#pragma unroll
        for (int e = 1; e < NEXP; e++) if (p[e] > p[i0]) i0 = e;
        int i1 = (i0 == 0) ? 1 : 0;
#pragma unroll
        for (int e = 0; e < NEXP; e++) if (e != i0 && p[e] > p[i1]) i1 = e;
        float w0 = p[i0], w1 = p[i1];
        float s = w0 + w1;
        w0 /= s; w1 /= s;
        g_topi[2 * t] = i0;     g_topw[2 * t] = w0;
        g_topi[2 * t + 1] = i1; g_topw[2 * t + 1] = w1;
    }
}

// ------- fused histogram + offsets + scatter + tile list (single block) -----
__global__ void k_scatter_fused() {
    __shared__ int hist[NEXP];
    __shared__ int off[NEXP];
    __shared__ int fill[NEXP];
    int tid = threadIdx.x;
    if (tid < NEXP) hist[tid] = 0;
    __syncthreads();
    for (int i = tid; i < 2 * T_TOK; i += blockDim.x)
        atomicAdd(&hist[g_topi[i]], 1);
    __syncthreads();
    if (tid == 0) {
        int s = 0;
        for (int e = 0; e < NEXP; e++) {
            g_offsets[e] = s; off[e] = s; fill[e] = 0; s += hist[e];
        }
        g_offsets[NEXP] = s;
        // dense m-tile work list
        int t = 0;
        for (int e = 0; e < NEXP; e++)
            for (int m0 = 0; m0 < hist[e]; m0 += BM)
                g_tiles[t++] = (e << 20) | m0;
        g_ntiles = t;
    }
    __syncthreads();
    for (int i = tid; i < 2 * T_TOK; i += blockDim.x) {
        int e = g_topi[i];
        int pos = off[e] + atomicAdd(&fill[e], 1);
        g_token[pos] = i >> 1;
        g_weight[pos] = g_topw[i];
    }
}

// ---------------- convert x + w1 (main stream) ----------------
__global__ void k_cvt_xw1(const float4* __restrict__ x,
                          const float4* __restrict__ w1,
                          __half2* __restrict__ ox,
                          __half2* __restrict__ ow1) {
    const int N_X = T_TOK * DDIM / 4;
    const int N_W = NEXP * HDIM * DDIM / 4;
    int i = blockIdx.x * blockDim.x + threadIdx.x;
    const float4* src;
    __half2* dst;
    int j;
    if (i < N_X)            { src = x;  dst = ox;  j = i; }
    else if (i < N_X + N_W) { src = w1; dst = ow1; j = i - N_X; }
    else return;
    float4 v = src[j];
    dst[2 * j]     = __floats2half2_rn(v.x, v.y);
    dst[2 * j + 1] = __floats2half2_rn(v.z, v.w);
}

// ---------------- convert w2 + zero out (side stream; overlaps GEMM1) -------
__global__ void k_cvt_w2z(const float4* __restrict__ w2,
                          __half2* __restrict__ ow2,
                          float4* __restrict__ outz) {
    const int N_O = T_TOK * DDIM / 4;
    const int N_W = NEXP * DDIM * HDIM / 4;
    int i = blockIdx.x * blockDim.x + threadIdx.x;
    if (i < N_O) { outz[i] = make_float4(0.f, 0.f, 0.f, 0.f); return; }
    i -= N_O;
    if (i >= N_W) return;
    float4 v = w2[i];
    ow2[2 * i]     = __floats2half2_rn(v.x, v.y);
    ow2[2 * i + 1] = __floats2half2_rn(v.z, v.w);
}

// ---------------- fp16 mma.sync grouped GEMM ----------------
// 3-stage cp.async ring, 1 barrier/chunk, modulo-free unroll-by-3,
// compacted tile list.  Fragments loaded per k-step (no manual double-buffer).
// 8 warps as 2(M) x 4(N): warp tile 64 x 32.  Split-K capable.
template <int KDIM, int NTOT, bool IS_G1, int KSL>
__global__ __launch_bounds__(256, 2) void k_gemm_mma(
    const __half* __restrict__ A, const __half* __restrict__ W,
    const float* __restrict__ bias, void* __restrict__ outp)
{
    constexpr int A_ST = BM * ASTRIDE;
    constexpr int B_ST = BN * ASTRIDE;
    constexpr int C = KDIM / KSL / BK;

    if (blockIdx.y >= (unsigned)g_ntiles) return;
    int tile = g_tiles[blockIdx.y];
    int e = tile >> 20;
    int m0 = tile & 0xFFFFF;
    int ksl = blockIdx.z;
    int koff = ksl * (KDIM / KSL);

    int base = g_offsets[e];
    int cnt = g_offsets[e + 1] - base;
    int n0 = blockIdx.x * BN;

    extern __shared__ __half smem[];
    uint32_t As_u32 = smem_u32(smem);                 // STAGES x A_ST
    uint32_t Bs_u32 = As_u32 + STAGES * A_ST * 2;     // STAGES x B_ST

    __shared__ int   stok[BM];
    __shared__ float swt[BM];

    int tid = threadIdx.x;
    int wid = tid >> 5, lane = tid & 31;
    int wm = wid & 1, wn = wid >> 1;

    if (tid < BM) {
        bool v = (m0 + tid < cnt);
        stok[tid] = v ? g_token[base + m0 + tid] : -1;
        swt[tid]  = v ? g_weight[base + m0 + tid] : 0.0f;
    }
    __syncthreads();

    const __half* Wbase = W + (size_t)e * NTOT * KDIM + (size_t)n0 * KDIM + koff;

    auto load_chunk = [&](int c, int buf) {
        int k0 = c * BK;
        uint32_t Ab = As_u32 + buf * A_ST * 2;
        uint32_t Bb = Bs_u32 + buf * B_ST * 2;
#pragma unroll
        for (int i = 0; i < 4; i++) {
            int idx = tid + i * 256;
            int row = idx >> 3, q = idx & 7;
            uint32_t dst = Ab + (row * ASTRIDE + q * 8) * 2;
            if (IS_G1) {
                int tok = stok[row];
                const __half* src = (tok >= 0) ? (A + (size_t)tok * KDIM + koff + k0 + q * 8) : A;
                cp16(dst, src, (tok >= 0) ? 16 : 0);
            } else {
                bool v = (m0 + row < cnt);
                const __half* src = v ? (A + (size_t)(base + m0 + row) * KDIM + koff + k0 + q * 8) : A;
                cp16(dst, src, v ? 16 : 0);
            }
        }
#pragma unroll
        for (int i = 0; i < 4; i++) {
            int idx = tid + i * 256;
            int row = idx >> 3, q = idx & 7;
            uint32_t dst = Bb + (row * ASTRIDE + q * 8) * 2;
            cp16(dst, Wbase + (size_t)row * KDIM + k0 + q * 8, 16);
        }
        CP_COMMIT();
    };

    float acc[4][4][4];
#pragma unroll
    for (int mt = 0; mt < 4; mt++)
#pragma unroll
        for (int nt = 0; nt < 4; nt++)
#pragma unroll
            for (int r = 0; r < 4; r++) acc[mt][nt][r] = 0.0f;

    load_chunk(0, 0);
    load_chunk(1, 1);

    // one pipeline step: consume stage `buf` for chunk `c`, prefetch c+2
    auto step = [&](int c, int buf) {
        if (c < C - 1) { CP_WAIT(1); } else { CP_WAIT(0); }
        __syncthreads();
        if (c + 2 < C) load_chunk(c + 2, (buf + 2) % STAGES);  // folds when buf literal

        uint32_t Ab = As_u32 + buf * A_ST * 2;
        uint32_t Bb = Bs_u32 + buf * B_ST * 2;

#pragma unroll
        for (int ks = 0; ks < BK / 16; ks++) {
            int kh = ks * 16 + ((lane >> 4) << 3);
            uint32_t a[4][4], b[2][4];
#pragma unroll
            for (int mt = 0; mt < 4; mt++) {
                int r = wm * 64 + mt * 16 + (lane & 15);
                ldmx4(a[mt], Ab + (r * ASTRIDE + kh) * 2);
            }
#pragma unroll
            for (int np = 0; np < 2; np++) {
                int r = wn * 32 + np * 16 + (lane & 15);
                ldmx4(b[np], Bb + (r * ASTRIDE + kh) * 2);
            }
#pragma unroll
            for (int mt = 0; mt < 4; mt++)
#pragma unroll
                for (int np = 0; np < 2; np++) {
                    mma16(acc[mt][2 * np + 0], a[mt], b[np][0], b[np][2]);
                    mma16(acc[mt][2 * np + 1], a[mt], b[np][1], b[np][3]);
                }
        }
    };

    // modulo-free steady state: 3 steps per iteration with literal stage ids
    int c = 0;
#pragma unroll 1
    for (; c + 3 <= C; c += 3) {
        step(c,     0);
        step(c + 1, 1);
        step(c + 2, 2);
    }
    if (c < C) { step(c, 0); c++; }
    if (c < C) { step(c, 1); }

    // epilogue
    bool add_bias = (ksl == 0);
#pragma unroll
    for (int mt = 0; mt < 4; mt++) {
#pragma unroll
        for (int nt = 0; nt < 4; nt++) {
#pragma unroll
            for (int half = 0; half < 2; half++) {
                int m = wm * 64 + mt * 16 + (lane >> 2) + half * 8;
                if (m0 + m >= cnt) continue;
                int ncol = n0 + wn * 32 + nt * 8 + (lane & 3) * 2;
                float b0 = add_bias ? bias[e * NTOT + ncol]     : 0.0f;
                float b1 = add_bias ? bias[e * NTOT + ncol + 1] : 0.0f;
                float v0 = acc[mt][nt][half * 2 + 0] + b0;
                float v1 = acc[mt][nt][half * 2 + 1] + b1;
                if (IS_G1) {
                    float g0 = 0.5f * v0 * (1.0f + erff(v0 * 0.70710678118654752f));
                    float g1 = 0.5f * v1 * (1.0f + erff(v1 * 0.70710678118654752f));
                    __half2* dst = (__half2*)((__half*)outp +
                                   (size_t)(base + m0 + m) * NTOT + ncol);
                    *dst = __floats2half2_rn(g0, g1);
                } else {
                    int tok = stok[m];
                    float w = swt[m];
                    float* o = (float*)outp + (size_t)tok * NTOT + ncol;
                    atomicAdd(o,     w * v0);
                    atomicAdd(o + 1, w * v1);
                }
            }
        }
    }
}

// ---------------- launch (R10 topology, compacted grids) ----------------
extern "C" void kernel_launch(void* const* d_in, const int* in_sizes, int n_in,
                              void* d_out, int out_size) {
    const float* x   = (const float*)d_in[0];
    const float* rw  = (const float*)d_in[1];
    const float* w1  = (const float*)d_in[2];
    const float* b1  = (const float*)d_in[3];
    const float* w2  = (const float*)d_in[4];
    const float* b2  = (const float*)d_in[5];
    float* out = (float*)d_out;

    const int SMEM_BYTES = STAGES * (BM + BN) * ASTRIDE * 2;   // 110592

    static cudaStream_t s_side = 0;
    static cudaEvent_t ev_fork = 0, ev_scat = 0, ev_cvt1 = 0, ev_w2 = 0;
    static int init_done = 0;
    if (!init_done) {
        cudaFuncSetAttribute(k_gemm_mma<DDIM, HDIM, true, 1>,
                             cudaFuncAttributeMaxDynamicSharedMemorySize, SMEM_BYTES);
        cudaFuncSetAttribute(k_gemm_mma<HDIM, DDIM, false, 2>,
                             cudaFuncAttributeMaxDynamicSharedMemorySize, SMEM_BYTES);
        cudaStreamCreateWithFlags(&s_side, cudaStreamNonBlocking);
        cudaEventCreateWithFlags(&ev_fork, cudaEventDisableTiming);
        cudaEventCreateWithFlags(&ev_scat, cudaEventDisableTiming);
        cudaEventCreateWithFlags(&ev_cvt1, cudaEventDisableTiming);
        cudaEventCreateWithFlags(&ev_w2,   cudaEventDisableTiming);
        init_done = 1;
    }

    __half *gh, *gxh, *gw1h, *gw2h;
    cudaGetSymbolAddress((void**)&gh,   g_h);
    cudaGetSymbolAddress((void**)&gxh,  g_xh);
    cudaGetSymbolAddress((void**)&gw1h, g_w1h);
    cudaGetSymbolAddress((void**)&gw2h, g_w2h);

    const int N_O = T_TOK * DDIM / 4;
    const int N_X = T_TOK * DDIM / 4;
    const int N_W = NEXP * HDIM * DDIM / 4;

    // fork side stream
    cudaEventRecord(ev_fork, 0);
    cudaStreamWaitEvent(s_side, ev_fork, 0);

    // main: convert x + w1
    k_cvt_xw1<<<(N_X + N_W + 255) / 256, 256>>>(
        (const float4*)x, (const float4*)w1, (__half2*)gxh, (__half2*)gw1h);
    cudaEventRecord(ev_cvt1, 0);

    // side: router + scatter (+ tile list), concurrent with cvt_xw1
    k_router<<<T_TOK / 8, 256, 0, s_side>>>(x, rw);
    k_scatter_fused<<<1, 1024, 0, s_side>>>();
    cudaEventRecord(ev_scat, s_side);

    // side: w2 convert + out zero AFTER cvt_xw1 completes -> overlaps GEMM1
    cudaStreamWaitEvent(s_side, ev_cvt1, 0);
    k_cvt_w2z<<<(N_O + N_W + 255) / 256, 256, 0, s_side>>>(
        (const float4*)w2, (__half2*)gw2h, (float4*)out);
    cudaEventRecord(ev_w2, s_side);

    // main: GEMM1 after scatter (compacted tile list)
    cudaStreamWaitEvent(0, ev_scat, 0);
    k_gemm_mma<DDIM, HDIM, true, 1>
        <<<dim3(HDIM / BN, MAXTILES, 1), 256, SMEM_BYTES>>>(gxh, gw1h, b1, gh);

    // main: GEMM2 after w2 convert (split-K = 2, compacted tile list)
    cudaStreamWaitEvent(0, ev_w2, 0);
    k_gemm_mma<HDIM, DDIM, false, 2>
        <<<dim3(DDIM / BN, MAXTILES, 2), 256, SMEM_BYTES>>>(gh, gw2h, b2, out);
}